// round 2
// baseline (speedup 1.0000x reference)
#include <cuda_runtime.h>
#include <math.h>

#define Bv 16
#define Sv 2048
#define Ev 256
#define Lv 2
#define NQv 8
#define FFNv 512
#define Cv 2
#define Mv (Bv*Sv)   // 32768 token rows

// Scratch (static device allocations; no cudaMalloc allowed)
__device__ float g_x[Mv*Ev];      // activations      (33.5 MB)
__device__ float g_y[Mv*Ev];      // gemm out scratch (33.5 MB)
__device__ float g_h[Mv*FFNv];    // ffn hidden       (67 MB)

// ---------------------------------------------------------------------------
// 1. embedding gather + sinusoidal positional encoding
// ---------------------------------------------------------------------------
__global__ void embed_pos_kernel(const int* __restrict__ tokens,
                                 const float* __restrict__ embed,
                                 float* __restrict__ x) {
    int idx = blockIdx.x * blockDim.x + threadIdx.x;
    if (idx >= Mv * Ev) return;
    int e   = idx & (Ev - 1);
    int row = idx >> 8;
    int s   = row & (Sv - 1);
    int tok = tokens[row];
    float i2 = (float)(e & ~1);
    float d  = expf(i2 * (-9.210340371976184f / 256.0f));  // 10000^{-i/dim}
    float arg = (float)s * d;
    float pe = (e & 1) ? cosf(arg) : sinf(arg);
    x[idx] = embed[tok * Ev + e] + pe;
}

// ---------------------------------------------------------------------------
// 2. Tiled SGEMM: C[M,N] = op(A)[M,K] @ B[K,N] + bias
//    MODE 0: op(A)=A           MODE 1: op(A)=cos(A + theta[k & 63])
//    Block tile 128x128, K-chunk 16, thread tile 8x8, 256 threads.
// ---------------------------------------------------------------------------
template<int MODE>
__global__ void __launch_bounds__(256, 2)
sgemm128(const float* __restrict__ A, const float* __restrict__ Bm,
         const float* __restrict__ bias, const float* __restrict__ theta,
         float* __restrict__ Cm, int M, int N, int K) {
    __shared__ float As[16][128];   // transposed: As[k][m]
    __shared__ float Bs[16][128];

    const int t    = threadIdx.x;
    const int tx   = t & 15;        // 0..15  -> col group
    const int ty   = t >> 4;        // 0..15  -> row group
    const int row0 = blockIdx.y * 128;
    const int col0 = blockIdx.x * 128;

    float acc[8][8];
#pragma unroll
    for (int i = 0; i < 8; i++)
#pragma unroll
        for (int j = 0; j < 8; j++) acc[i][j] = 0.f;

    for (int k0 = 0; k0 < K; k0 += 16) {
        // load A tile (128 rows x 16 k), apply transform, store transposed
#pragma unroll
        for (int p = 0; p < 2; p++) {
            int idx = p * 256 + t;
            int r   = idx >> 2;           // 0..127
            int kq  = idx & 3;            // 0..3  (float4 within 16-k row)
            float4 a = *(const float4*)(A + (size_t)(row0 + r) * K + k0 + kq * 4);
            if (MODE == 1) {
                int kb = k0 + kq * 4;
                a.x = cosf(a.x + theta[(kb + 0) & 63]);
                a.y = cosf(a.y + theta[(kb + 1) & 63]);
                a.z = cosf(a.z + theta[(kb + 2) & 63]);
                a.w = cosf(a.w + theta[(kb + 3) & 63]);
            }
            As[kq * 4 + 0][r] = a.x;
            As[kq * 4 + 1][r] = a.y;
            As[kq * 4 + 2][r] = a.z;
            As[kq * 4 + 3][r] = a.w;
        }
        // load B tile (16 k x 128 cols)
#pragma unroll
        for (int p = 0; p < 2; p++) {
            int idx = p * 256 + t;
            int kr  = idx >> 5;           // 0..15
            int cq  = idx & 31;           // float4 col group
            float4 b = *(const float4*)(Bm + (size_t)(k0 + kr) * N + col0 + cq * 4);
            *(float4*)&Bs[kr][cq * 4] = b;
        }
        __syncthreads();

#pragma unroll
        for (int kk = 0; kk < 16; kk++) {
            float4 a0 = *(const float4*)&As[kk][ty * 8];
            float4 a1 = *(const float4*)&As[kk][ty * 8 + 4];
            float4 b0 = *(const float4*)&Bs[kk][tx * 8];
            float4 b1 = *(const float4*)&Bs[kk][tx * 8 + 4];
            float av[8] = {a0.x, a0.y, a0.z, a0.w, a1.x, a1.y, a1.z, a1.w};
            float bv[8] = {b0.x, b0.y, b0.z, b0.w, b1.x, b1.y, b1.z, b1.w};
#pragma unroll
            for (int i = 0; i < 8; i++)
#pragma unroll
                for (int j = 0; j < 8; j++)
                    acc[i][j] = fmaf(av[i], bv[j], acc[i][j]);
        }
        __syncthreads();
    }

    // epilogue: + bias, store
    float bj[8];
#pragma unroll
    for (int j = 0; j < 8; j++) bj[j] = bias[col0 + tx * 8 + j];
#pragma unroll
    for (int i = 0; i < 8; i++) {
        int row = row0 + ty * 8 + i;
        float4 o0 = make_float4(acc[i][0] + bj[0], acc[i][1] + bj[1],
                                acc[i][2] + bj[2], acc[i][3] + bj[3]);
        float4 o1 = make_float4(acc[i][4] + bj[4], acc[i][5] + bj[5],
                                acc[i][6] + bj[6], acc[i][7] + bj[7]);
        *(float4*)(Cm + (size_t)row * N + col0 + tx * 8)     = o0;
        *(float4*)(Cm + (size_t)row * N + col0 + tx * 8 + 4) = o1;
    }
}

// ---------------------------------------------------------------------------
// 3. residual + LayerNorm: out = LN(x + y) * g + b    (warp per row, E=256)
// ---------------------------------------------------------------------------
__global__ void ln_resid_kernel(const float* __restrict__ x,
                                const float* __restrict__ y,
                                const float* __restrict__ g,
                                const float* __restrict__ b,
                                float* __restrict__ out) {
    int warp = (blockIdx.x * blockDim.x + threadIdx.x) >> 5;
    int lane = threadIdx.x & 31;
    if (warp >= Mv) return;
    const float4* xr = (const float4*)(x + (size_t)warp * Ev);
    const float4* yr = (const float4*)(y + (size_t)warp * Ev);
    float4 x0 = xr[lane], x1 = xr[lane + 32];
    float4 y0 = yr[lane], y1 = yr[lane + 32];
    float v[8] = {x0.x + y0.x, x0.y + y0.y, x0.z + y0.z, x0.w + y0.w,
                  x1.x + y1.x, x1.y + y1.y, x1.z + y1.z, x1.w + y1.w};
    float sum = 0.f;
#pragma unroll
    for (int i = 0; i < 8; i++) sum += v[i];
#pragma unroll
    for (int o = 16; o; o >>= 1) sum += __shfl_xor_sync(0xffffffffu, sum, o);
    float m = sum * (1.0f / Ev);
    float vs = 0.f;
#pragma unroll
    for (int i = 0; i < 8; i++) { float d = v[i] - m; vs += d * d; }
#pragma unroll
    for (int o = 16; o; o >>= 1) vs += __shfl_xor_sync(0xffffffffu, vs, o);
    float inv = rsqrtf(vs * (1.0f / Ev) + 1e-5f);

    const float4* gr = (const float4*)g;
    const float4* br = (const float4*)b;
    float4 g0 = gr[lane], g1 = gr[lane + 32];
    float4 b0 = br[lane], b1 = br[lane + 32];
    float4 o0, o1;
    o0.x = (v[0] - m) * inv * g0.x + b0.x;
    o0.y = (v[1] - m) * inv * g0.y + b0.y;
    o0.z = (v[2] - m) * inv * g0.z + b0.z;
    o0.w = (v[3] - m) * inv * g0.w + b0.w;
    o1.x = (v[4] - m) * inv * g1.x + b1.x;
    o1.y = (v[5] - m) * inv * g1.y + b1.y;
    o1.z = (v[6] - m) * inv * g1.z + b1.z;
    o1.w = (v[7] - m) * inv * g1.w + b1.w;
    float4* orow = (float4*)(out + (size_t)warp * Ev);
    orow[lane] = o0; orow[lane + 32] = o1;
}

// ---------------------------------------------------------------------------
// 4. FFN hidden: h = relu( (cos(x[:, :8]) * cos(theta)) @ W1 + b1 )
//    block handles 8 rows, 256 threads
// ---------------------------------------------------------------------------
__global__ void ffn_h_kernel(const float* __restrict__ x,
                             const float* __restrict__ ffn_theta,
                             const float* __restrict__ W1,
                             const float* __restrict__ b1,
                             float* __restrict__ h) {
    int row0 = blockIdx.x * 8;
    int t = threadIdx.x;
    __shared__ float qs[8][NQv];
    if (t < 64) {
        int m = t >> 3, n = t & 7;
        qs[m][n] = cosf(x[(size_t)(row0 + m) * Ev + n]) * cosf(ffn_theta[n]);
    }
    __syncthreads();
#pragma unroll
    for (int fo = 0; fo < FFNv; fo += 256) {
        int f = fo + t;
        float w[NQv];
#pragma unroll
        for (int n = 0; n < NQv; n++) w[n] = W1[n * FFNv + f];
        float bb = b1[f];
#pragma unroll
        for (int m = 0; m < 8; m++) {
            float acc = bb;
#pragma unroll
            for (int n = 0; n < NQv; n++) acc = fmaf(qs[m][n], w[n], acc);
            h[(size_t)(row0 + m) * FFNv + f] = fmaxf(acc, 0.f);
        }
    }
}

// ---------------------------------------------------------------------------
// 5. pooled mean + classifier
// ---------------------------------------------------------------------------
#define POOL_SPLIT 32
__global__ void pool1_kernel(const float* __restrict__ x, float* __restrict__ part) {
    int b = blockIdx.x, sp = blockIdx.y;
    int e = threadIdx.x;
    size_t base = ((size_t)b * Sv + (size_t)sp * (Sv / POOL_SPLIT)) * Ev + e;
    float s = 0.f;
#pragma unroll 4
    for (int i = 0; i < Sv / POOL_SPLIT; i++) s += x[base + (size_t)i * Ev];
    part[((size_t)b * POOL_SPLIT + sp) * Ev + e] = s;
}

__global__ void pool2_kernel(const float* __restrict__ part,
                             const float* __restrict__ cls_w,
                             const float* __restrict__ cls_b,
                             float* __restrict__ out) {
    int b = blockIdx.x;
    int e = threadIdx.x;
    float s = 0.f;
#pragma unroll
    for (int i = 0; i < POOL_SPLIT; i++) s += part[((size_t)b * POOL_SPLIT + i) * Ev + e];
    s *= (1.0f / Sv);
    __shared__ float red[Ev];
#pragma unroll
    for (int c = 0; c < Cv; c++) {
        red[e] = s * cls_w[e * Cv + c];
        __syncthreads();
        for (int o = 128; o; o >>= 1) {
            if (e < o) red[e] += red[e + o];
            __syncthreads();
        }
        if (e == 0) out[b * Cv + c] = red[0] + cls_b[c];
        __syncthreads();
    }
}

// ---------------------------------------------------------------------------
extern "C" void kernel_launch(void* const* d_in, const int* in_sizes, int n_in,
                              void* d_out, int out_size) {
    const int*   tokens     = (const int*)  d_in[0];
    const float* embed      = (const float*)d_in[1];
    const float* attn_theta = (const float*)d_in[2];
    const float* combine_w  = (const float*)d_in[3];
    const float* combine_b  = (const float*)d_in[4];
    const float* ffn_theta  = (const float*)d_in[5];
    const float* lin1_w     = (const float*)d_in[6];
    const float* lin1_b     = (const float*)d_in[7];
    const float* lin2_w     = (const float*)d_in[8];
    const float* lin2_b     = (const float*)d_in[9];
    const float* ln1_g      = (const float*)d_in[10];
    const float* ln1_b      = (const float*)d_in[11];
    const float* ln2_g      = (const float*)d_in[12];
    const float* ln2_b      = (const float*)d_in[13];
    const float* cls_w      = (const float*)d_in[14];
    const float* cls_b      = (const float*)d_in[15];
    float* out = (float*)d_out;

    float *x, *y, *h;
    cudaGetSymbolAddress((void**)&x, g_x);
    cudaGetSymbolAddress((void**)&y, g_y);
    cudaGetSymbolAddress((void**)&h, g_h);

    // 1. embed + positional encoding
    embed_pos_kernel<<<(Mv * Ev + 255) / 256, 256>>>(tokens, embed, x);

    dim3 gemmGridE(Ev / 128, Mv / 128);   // attn / lin2 GEMM (N=256)

    for (int l = 0; l < Lv; l++) {
        // attention: y = cos(x + theta) @ combine_w + combine_b
        sgemm128<1><<<gemmGridE, 256>>>(x, combine_w + (size_t)l * Ev * Ev,
                                        combine_b + l * Ev, attn_theta + l * 64,
                                        y, Mv, Ev, Ev);
        // x = LN(x + y)
        ln_resid_kernel<<<Mv / 8, 256>>>(x, y, ln1_g + l * Ev, ln1_b + l * Ev, x);
        // h = relu(q @ lin1_w + b1)
        ffn_h_kernel<<<Mv / 8, 256>>>(x, ffn_theta + l * NQv,
                                      lin1_w + (size_t)l * NQv * FFNv,
                                      lin1_b + l * FFNv, h);
        // y = h @ lin2_w + b2
        sgemm128<0><<<gemmGridE, 256>>>(h, lin2_w + (size_t)l * FFNv * Ev,
                                        lin2_b + l * Ev, (const float*)0,
                                        y, Mv, Ev, FFNv);
        // x = LN(x + y)
        ln_resid_kernel<<<Mv / 8, 256>>>(x, y, ln2_g + l * Ev, ln2_b + l * Ev, x);
    }

    // pooled mean + classifier
    dim3 pgrid(Bv, POOL_SPLIT);
    pool1_kernel<<<pgrid, Ev>>>(x, y);
    pool2_kernel<<<Bv, Ev>>>(y, cls_w, cls_b, out);
}